// round 3
// baseline (speedup 1.0000x reference)
#include <cuda_runtime.h>
#include <math.h>

// ParamEvaler: 64 vmapped CNNs (conv5x5 -> relu -> maxpool2x2 -> dense10 ->
// log_softmax) over a shared 128-image batch.
// params: [64, 46922] f32  (w_conv 800 | b_conv 32 | w_dense 46080 | b_dense 10)
// batch : [128, 1, 28, 28] f32
// out   : [64, 128, 10] f32
//
// One CTA per (init, 64-image half), 128 CTAs = one wave. Dense weights +
// double image + double pool tiles live in SMEM (232,128 B, occupancy 1).
// Conv: packed fma.rn.f32x2 over the two horizontal conv outputs of each
// pool cell; vertical 3-pool-cell strips share a 10-row image window via
// sliding-window accumulators. Dense: 2 images per weight read (weight SMEM
// traffic halved). Next image pair prefetched to registers under dense.

#define NTHREADS 512
typedef unsigned long long u64;

__device__ __forceinline__ u64 fma2(u64 a, u64 b, u64 c) {
    u64 d;
    asm("fma.rn.f32x2 %0, %1, %2, %3;" : "=l"(d) : "l"(a), "l"(b), "l"(c));
    return d;
}
__device__ __forceinline__ u64 pack2(float lo, float hi) {
    u64 r;
    asm("mov.b64 %0, {%1, %2};" : "=l"(r) : "f"(lo), "f"(hi));
    return r;
}
__device__ __forceinline__ float2 unpack2(u64 v) {
    float2 r;
    asm("mov.b64 {%0, %1}, %2;" : "=f"(r.x), "=f"(r.y) : "l"(v));
    return r;
}

// SMEM layout (float offsets; all u64-accessed regions at even offsets)
#define S_WD     0              // 46080 : dense weights [10][4608]
#define S_WC     46080          // 800   : conv weights [32][25]
#define S_BC     46880          // 32    : conv bias
#define S_BD     46912          // 16    : dense bias (padded)
#define S_IMG    46928          // 1568  : 2 images [2][784]
#define S_POOL   48496          // 9216  : 2 pooled tiles [2][32][12][12]
#define S_WSUM   57712          // 320   : per-warp dense partials [2][16][10]
#define SMEM_FLOATS 58032
#define SMEM_BYTES (SMEM_FLOATS*4)      // 232,128 B <= 232,448 B opt-in

__global__ __launch_bounds__(NTHREADS, 1)
void paramevaler_fused(const float* __restrict__ params,
                       const float* __restrict__ batch,
                       float* __restrict__ out) {
    extern __shared__ float smem[];
    float* s_wc   = smem + S_WC;
    float* s_img  = smem + S_IMG;
    float* s_pool = smem + S_POOL;
    float* s_bc   = smem + S_BC;
    float* s_bd   = smem + S_BD;
    float* s_wsum = smem + S_WSUM;

    const int tid = threadIdx.x;
    const int i   = blockIdx.y;          // init 0..63
    const int n0  = blockIdx.x * 64;     // image half base

    const float* P = params + (size_t)i * 46922;

    // ---- prologue: stage per-init weights ----
    {
        // dense weights: 46080 f32, float2-aligned (46922*i even, +832 even)
        const float2* gw = (const float2*)(P + 832);
        float2* sw = (float2*)(smem + S_WD);
        for (int idx = tid; idx < 23040; idx += NTHREADS) sw[idx] = gw[idx];
        for (int k = tid; k < 800; k += NTHREADS) s_wc[k] = P[k];
        if (tid < 32) s_bc[tid] = P[800 + tid];
        if (tid < 10) s_bd[tid] = P[46912 + tid];
    }

    const int c   = tid >> 4;    // channel 0..31 (2 channels per warp)
    const int l16 = tid & 15;
    const int wid = tid >> 5;
    const int lid = tid & 31;

    // ---- prefetch + commit image pair 0 ----
    const float2* gb2 = (const float2*)batch;       // batch float2-aligned
    float2* s_img2 = (float2*)s_img;
    float2 st0, st1;
    {
        int base = n0 * 392;                        // float2 index of pair 0
        st0 = gb2[base + tid];
        if (tid + NTHREADS < 784) st1 = gb2[base + tid + NTHREADS];
    }
    __syncthreads();            // weights staged
    s_img2[tid] = st0;
    if (tid + NTHREADS < 784) s_img2[tid + NTHREADS] = st1;
    __syncthreads();            // pair-0 image ready
    const float bcv = s_bc[c];

    for (int p = 0; p < 32; ++p) {
        // ---- conv weights -> packed {w,w} registers ----
        u64 w2[25];
        #pragma unroll
        for (int k = 0; k < 25; ++k) {
            float w = s_wc[c * 25 + k];
            w2[k] = pack2(w, w);
        }

        // ---- conv5x5 + maxpool2x2 + bias + relu for both images ----
        #pragma unroll
        for (int b = 0; b < 2; ++b) {
            const float* img = s_img + b * 784;
            #pragma unroll
            for (int s = 0; s < 3; ++s) {
                const int stx = l16 + s * 16;       // strip 0..47
                const int pwi = stx % 12;           // pool column
                const int phg = stx / 12;           // pool-row group (3 rows)
                // image window: rows 6*phg..6*phg+9, cols 2*pwi..2*pwi+5
                const u64* rp = (const u64*)(img + phg * 168 + pwi * 2);
                u64 acc[6];                         // conv rows 6*phg+t
                #pragma unroll
                for (int t = 0; t < 6; ++t) acc[t] = 0ULL;
                #pragma unroll
                for (int r = 0; r < 10; ++r) {
                    u64 p0 = rp[0], p1 = rp[1], p2 = rp[2];
                    rp += 14;                       // next image row
                    float2 f0 = unpack2(p0), f1 = unpack2(p1), f2v = unpack2(p2);
                    u64 v1 = pack2(f0.y, f1.x);
                    u64 v3 = pack2(f1.y, f2v.x);
                    #pragma unroll
                    for (int t = 0; t < 6; ++t) {
                        if (t <= r && r - t <= 4) { // conv row t, ky = r-t
                            const int b5 = (r - t) * 5;
                            acc[t] = fma2(w2[b5 + 0], p0, acc[t]);
                            acc[t] = fma2(w2[b5 + 1], v1, acc[t]);
                            acc[t] = fma2(w2[b5 + 2], p1, acc[t]);
                            acc[t] = fma2(w2[b5 + 3], v3, acc[t]);
                            acc[t] = fma2(w2[b5 + 4], p2, acc[t]);
                        }
                    }
                }
                #pragma unroll
                for (int k = 0; k < 3; ++k) {       // 3 pool cells per strip
                    float2 x0 = unpack2(acc[2 * k]);
                    float2 x1 = unpack2(acc[2 * k + 1]);
                    float m = fmaxf(fmaxf(x0.x, x0.y), fmaxf(x1.x, x1.y));
                    s_pool[b * 4608 + c * 144 + (phg * 3 + k) * 12 + pwi] =
                        fmaxf(m + bcv, 0.0f);
                }
            }
        }

        // ---- prefetch next image pair (hidden under dense) ----
        if (p + 1 < 32) {
            int base = (n0 + 2 * (p + 1)) * 392;
            st0 = gb2[base + tid];
            if (tid + NTHREADS < 784) st1 = gb2[base + tid + NTHREADS];
        }
        __syncthreads();        // pool tiles ready

        // ---- dense 10x4608, 2 images per weight read ----
        u64 dacc[2][10];
        #pragma unroll
        for (int b = 0; b < 2; ++b)
            #pragma unroll
            for (int o = 0; o < 10; ++o) dacc[b][o] = 0ULL;
        const u64* wdp = (const u64*)(smem + S_WD);
        const u64* pp0 = (const u64*)s_pool;
        const u64* pp1 = pp0 + 2304;
        for (int jd = tid; jd < 2304; jd += NTHREADS) {
            u64 a = pp0[jd], bb = pp1[jd];
            #pragma unroll
            for (int o = 0; o < 10; ++o) {
                u64 w = wdp[o * 2304 + jd];
                dacc[0][o] = fma2(w, a,  dacc[0][o]);
                dacc[1][o] = fma2(w, bb, dacc[1][o]);
            }
        }
        // deterministic reduction: horizontal add + warp shfl + per-warp slot
        #pragma unroll
        for (int b = 0; b < 2; ++b)
            #pragma unroll
            for (int o = 0; o < 10; ++o) {
                float2 h = unpack2(dacc[b][o]);
                float s = h.x + h.y;
                #pragma unroll
                for (int off = 16; off > 0; off >>= 1)
                    s += __shfl_xor_sync(0xffffffffu, s, off);
                if (lid == 0) s_wsum[b * 160 + wid * 10 + o] = s;
            }
        __syncthreads();        // partials ready

        // ---- combine 16 warps + log_softmax (warp b -> image b) ----
        if (wid < 2) {
            const int b = wid;
            float v = -3.0e38f;
            if (lid < 10) {
                v = s_bd[lid];
                #pragma unroll
                for (int w = 0; w < 16; ++w) v += s_wsum[b * 160 + w * 10 + lid];
            }
            float m = v;
            #pragma unroll
            for (int off = 16; off > 0; off >>= 1)
                m = fmaxf(m, __shfl_xor_sync(0xffffffffu, m, off));
            float e = (lid < 10) ? expf(v - m) : 0.0f;
            float s = e;
            #pragma unroll
            for (int off = 16; off > 0; off >>= 1)
                s += __shfl_xor_sync(0xffffffffu, s, off);
            if (lid < 10) {
                int n = n0 + 2 * p + b;
                out[((size_t)i * 128 + n) * 10 + lid] = v - m - logf(s);
            }
        }

        // ---- commit prefetched pair ----
        if (p + 1 < 32) {
            s_img2[tid] = st0;
            if (tid + NTHREADS < 784) s_img2[tid + NTHREADS] = st1;
        }
        __syncthreads();        // img committed / wsum+pool protected
    }
}

extern "C" void kernel_launch(void* const* d_in, const int* in_sizes, int n_in,
                              void* d_out, int out_size) {
    const float* params = (const float*)d_in[0];
    const float* batch  = (const float*)d_in[1];
    float* out = (float*)d_out;
    (void)in_sizes; (void)n_in; (void)out_size;

    cudaFuncSetAttribute(paramevaler_fused,
                         cudaFuncAttributeMaxDynamicSharedMemorySize, SMEM_BYTES);
    dim3 grid(2, 64);   // (batch half, init) -> 128 CTAs, one wave on 148+ SMs
    paramevaler_fused<<<grid, NTHREADS, SMEM_BYTES>>>(params, batch, out);
}

// round 16
// speedup vs baseline: 1.1529x; 1.1529x over previous
#include <cuda_runtime.h>
#include <math.h>

// ParamEvaler: 64 vmapped CNNs (conv5x5 -> relu -> maxpool2x2 -> dense10 ->
// log_softmax) over a shared 128-image batch.
// params: [64, 46922] f32  (w_conv 800 | b_conv 32 | w_dense 46080 | b_dense 10)
// batch : [128, 1, 28, 28] f32
// out   : [64, 128, 10] f32
//
// One CTA per (init, 64-image half), 128 CTAs = one wave, occupancy 1.
// R16 = R4 design, thirteenth submit (broker timeouts; never executed). vs
// the 292.9us baseline whose profile showed L1=72% binding: conv threads own
// a 3x3 pool block (10x10 image window, 50 LDS.64/img vs 90); dense uses
// LDS.128 (half the load instructions).

#define NTHREADS 512
typedef unsigned long long u64;

__device__ __forceinline__ u64 fma2(u64 a, u64 b, u64 c) {
    u64 d;
    asm("fma.rn.f32x2 %0, %1, %2, %3;" : "=l"(d) : "l"(a), "l"(b), "l"(c));
    return d;
}
__device__ __forceinline__ u64 pack2(float lo, float hi) {
    u64 r;
    asm("mov.b64 %0, {%1, %2};" : "=l"(r) : "f"(lo), "f"(hi));
    return r;
}
__device__ __forceinline__ float2 unpack2(u64 v) {
    float2 r;
    asm("mov.b64 {%0, %1}, %2;" : "=f"(r.x), "=f"(r.y) : "l"(v));
    return r;
}

// SMEM layout (float offsets; u64 regions even, float4 regions 4-multiple)
#define S_WD     0              // 46080 : dense weights [10][4608]
#define S_WC     46080          // 800   : conv weights [32][25]
#define S_BC     46880          // 32    : conv bias
#define S_BD     46912          // 16    : dense bias (padded)
#define S_IMG    46928          // 1568  : 2 images [2][784]
#define S_POOL   48496          // 9216  : 2 pooled tiles [2][32][12][12]
#define S_WSUM   57712          // 320   : per-warp dense partials [2][16][10]
#define SMEM_FLOATS 58032
#define SMEM_BYTES (SMEM_FLOATS*4)      // 232,128 B <= 232,448 B opt-in

__global__ __launch_bounds__(NTHREADS, 1)
void paramevaler_fused(const float* __restrict__ params,
                       const float* __restrict__ batch,
                       float* __restrict__ out) {
    extern __shared__ float smem[];
    float* s_wc   = smem + S_WC;
    float* s_img  = smem + S_IMG;
    float* s_pool = smem + S_POOL;
    float* s_bc   = smem + S_BC;
    float* s_bd   = smem + S_BD;
    float* s_wsum = smem + S_WSUM;

    const int tid = threadIdx.x;
    const int i   = blockIdx.y;          // init 0..63
    const int n0  = blockIdx.x * 64;     // image half base

    const float* P = params + (size_t)i * 46922;

    // ---- prologue: stage per-init weights ----
    {
        const float2* gw = (const float2*)(P + 832);   // float2-aligned
        float2* sw = (float2*)(smem + S_WD);
        for (int idx = tid; idx < 23040; idx += NTHREADS) sw[idx] = gw[idx];
        for (int k = tid; k < 800; k += NTHREADS) s_wc[k] = P[k];
        if (tid < 32) s_bc[tid] = P[800 + tid];
        if (tid < 10) s_bd[tid] = P[46912 + tid];
    }

    const int c   = tid >> 4;    // channel 0..31 (2 channels per warp)
    const int l16 = tid & 15;
    const int wid = tid >> 5;
    const int lid = tid & 31;
    const int bh  = l16 >> 2;    // pool-block row 0..3
    const int bw  = l16 & 3;     // pool-block col 0..3

    // ---- prefetch + commit image pair 0 ----
    const float2* gb2 = (const float2*)batch;
    float2* s_img2 = (float2*)s_img;
    float2 st0, st1;
    {
        int base = n0 * 392;
        st0 = gb2[base + tid];
        if (tid + NTHREADS < 784) st1 = gb2[base + tid + NTHREADS];
    }
    __syncthreads();            // weights staged
    s_img2[tid] = st0;
    if (tid + NTHREADS < 784) s_img2[tid + NTHREADS] = st1;
    __syncthreads();            // pair-0 image ready
    const float bcv = s_bc[c];

    for (int p = 0; p < 32; ++p) {
        // ---- conv weights -> packed {w,w} registers ----
        u64 w2[25];
        #pragma unroll
        for (int k = 0; k < 25; ++k) {
            float w = s_wc[c * 25 + k];
            w2[k] = pack2(w, w);
        }

        // ---- conv5x5 + maxpool2x2 + bias + relu, 3x3 pool block/thread ----
        #pragma unroll
        for (int b = 0; b < 2; ++b) {
            const float* img = s_img + b * 784;
            // image window: rows 6bh..6bh+9, cols 6bw..6bw+9
            const u64* rp = (const u64*)(img + bh * 168 + bw * 6);
            u64 acc[18];                 // [t*3+m]: conv row t(0..5), col pair m(0..2)
            #pragma unroll
            for (int t = 0; t < 18; ++t) acc[t] = 0ULL;
            #pragma unroll
            for (int r = 0; r < 10; ++r) {
                u64 q0 = rp[0], q1 = rp[1], q2 = rp[2], q3 = rp[3], q4 = rp[4];
                rp += 14;                // next image row (28 floats)
                float2 f0 = unpack2(q0), f1 = unpack2(q1), f2v = unpack2(q2),
                       f3 = unpack2(q3), f4 = unpack2(q4);
                u64 m1 = pack2(f0.y, f1.x);
                u64 m3 = pack2(f1.y, f2v.x);
                u64 m5 = pack2(f2v.y, f3.x);
                u64 m7 = pack2(f3.y, f4.x);
                #pragma unroll
                for (int t = 0; t < 6; ++t) {
                    if (t <= r && r - t <= 4) {      // conv row t, ky = r-t
                        const int b5 = (r - t) * 5;
                        // col pair 0 (cols 0,1): operand offsets 0..4
                        acc[t*3+0] = fma2(w2[b5+0], q0, acc[t*3+0]);
                        acc[t*3+0] = fma2(w2[b5+1], m1, acc[t*3+0]);
                        acc[t*3+0] = fma2(w2[b5+2], q1, acc[t*3+0]);
                        acc[t*3+0] = fma2(w2[b5+3], m3, acc[t*3+0]);
                        acc[t*3+0] = fma2(w2[b5+4], q2, acc[t*3+0]);
                        // col pair 1 (cols 2,3): offsets 2..6
                        acc[t*3+1] = fma2(w2[b5+0], q1, acc[t*3+1]);
                        acc[t*3+1] = fma2(w2[b5+1], m3, acc[t*3+1]);
                        acc[t*3+1] = fma2(w2[b5+2], q2, acc[t*3+1]);
                        acc[t*3+1] = fma2(w2[b5+3], m5, acc[t*3+1]);
                        acc[t*3+1] = fma2(w2[b5+4], q3, acc[t*3+1]);
                        // col pair 2 (cols 4,5): offsets 4..8
                        acc[t*3+2] = fma2(w2[b5+0], q2, acc[t*3+2]);
                        acc[t*3+2] = fma2(w2[b5+1], m5, acc[t*3+2]);
                        acc[t*3+2] = fma2(w2[b5+2], q3, acc[t*3+2]);
                        acc[t*3+2] = fma2(w2[b5+3], m7, acc[t*3+2]);
                        acc[t*3+2] = fma2(w2[b5+4], q4, acc[t*3+2]);
                    }
                }
            }
            // pool cell (3bh+kr, 3bw+kc) = max over acc[2kr][kc], acc[2kr+1][kc]
            #pragma unroll
            for (int kr = 0; kr < 3; ++kr)
                #pragma unroll
                for (int kc = 0; kc < 3; ++kc) {
                    float2 x0 = unpack2(acc[(2*kr)*3 + kc]);
                    float2 x1 = unpack2(acc[(2*kr+1)*3 + kc]);
                    float m = fmaxf(fmaxf(x0.x, x0.y), fmaxf(x1.x, x1.y));
                    s_pool[b * 4608 + c * 144 + (3*bh+kr) * 12 + 3*bw+kc] =
                        fmaxf(m + bcv, 0.0f);
                }
        }

        // ---- prefetch next image pair (hidden under dense) ----
        if (p + 1 < 32) {
            int base = (n0 + 2 * (p + 1)) * 392;
            st0 = gb2[base + tid];
            if (tid + NTHREADS < 784) st1 = gb2[base + tid + NTHREADS];
        }
        __syncthreads();        // pool tiles ready

        // ---- dense 10x4608 via LDS.128, 2 images per weight read ----
        u64 dacc[2][10];
        #pragma unroll
        for (int b = 0; b < 2; ++b)
            #pragma unroll
            for (int o = 0; o < 10; ++o) dacc[b][o] = 0ULL;
        const float4* wq  = (const float4*)(smem + S_WD);
        const float4* pq0 = (const float4*)s_pool;
        const float4* pq1 = pq0 + 1152;
        for (int jd = tid; jd < 1152; jd += NTHREADS) {
            float4 a = pq0[jd], bb = pq1[jd];
            u64 a01 = pack2(a.x, a.y),  a23 = pack2(a.z, a.w);
            u64 b01 = pack2(bb.x, bb.y), b23 = pack2(bb.z, bb.w);
            #pragma unroll
            for (int o = 0; o < 10; ++o) {
                float4 w = wq[o * 1152 + jd];
                u64 w01 = pack2(w.x, w.y), w23 = pack2(w.z, w.w);
                dacc[0][o] = fma2(w01, a01, dacc[0][o]);
                dacc[0][o] = fma2(w23, a23, dacc[0][o]);
                dacc[1][o] = fma2(w01, b01, dacc[1][o]);
                dacc[1][o] = fma2(w23, b23, dacc[1][o]);
            }
        }
        // deterministic reduction: horizontal add + warp shfl + per-warp slot
        #pragma unroll
        for (int b = 0; b < 2; ++b)
            #pragma unroll
            for (int o = 0; o < 10; ++o) {
                float2 h = unpack2(dacc[b][o]);
                float s = h.x + h.y;
                #pragma unroll
                for (int off = 16; off > 0; off >>= 1)
                    s += __shfl_xor_sync(0xffffffffu, s, off);
                if (lid == 0) s_wsum[b * 160 + wid * 10 + o] = s;
            }
        __syncthreads();        // partials ready

        // ---- combine 16 warps + log_softmax (warp b -> image b) ----
        if (wid < 2) {
            const int b = wid;
            float v = -3.0e38f;
            if (lid < 10) {
                v = s_bd[lid];
                #pragma unroll
                for (int w = 0; w < 16; ++w) v += s_wsum[b * 160 + w * 10 + lid];
            }
            float m = v;
            #pragma unroll
            for (int off = 16; off > 0; off >>= 1)
                m = fmaxf(m, __shfl_xor_sync(0xffffffffu, m, off));
            float e = (lid < 10) ? expf(v - m) : 0.0f;
            float s = e;
            #pragma unroll
            for (int off = 16; off > 0; off >>= 1)
                s += __shfl_xor_sync(0xffffffffu, s, off);
            if (lid < 10) {
                int n = n0 + 2 * p + b;
                out[((size_t)i * 128 + n) * 10 + lid] = v - m - logf(s);
            }
        }

        // ---- commit prefetched pair ----
        if (p + 1 < 32) {
            s_img2[tid] = st0;
            if (tid + NTHREADS < 784) s_img2[tid + NTHREADS] = st1;
        }
        __syncthreads();        // img committed / wsum+pool protected
    }
}

extern "C" void kernel_launch(void* const* d_in, const int* in_sizes, int n_in,
                              void* d_out, int out_size) {
    const float* params = (const float*)d_in[0];
    const float* batch  = (const float*)d_in[1];
    float* out = (float*)d_out;
    (void)in_sizes; (void)n_in; (void)out_size;

    cudaFuncSetAttribute(paramevaler_fused,
                         cudaFuncAttributeMaxDynamicSharedMemorySize, SMEM_BYTES);
    dim3 grid(2, 64);   // (batch half, init) -> 128 CTAs, one wave
    paramevaler_fused<<<grid, NTHREADS, SMEM_BYTES>>>(params, batch, out);
}